// round 1
// baseline (speedup 1.0000x reference)
#include <cuda_runtime.h>
#include <math.h>

// Problem constants
#define Bn 2
#define Sn 2048
#define Dn 768
#define Hn 12
#define DHn 64
#define Fn 3072
#define Ln 2
#define BSn (Bn*Sn)          // 4096
#define BHn (Bn*Hn)          // 24

// ---------------- scratch (allocation-free) ----------------
__device__ float g_h [BSn*Dn];
__device__ float g_q [BSn*Dn];
__device__ float g_k [BSn*Dn];
__device__ float g_v [BSn*Dn];
__device__ float g_qh[BSn*Dn];
__device__ float g_kh[BSn*Dn];
__device__ float g_vh[BSn*Dn];
__device__ float g_oh[BSn*Dn];
__device__ float g_o [BSn*Dn];
__device__ float g_t [BSn*Dn];
__device__ float g_ff[BSn*Fn];

// ---------------- embedding + sinusoidal PE ----------------
__global__ void embed_kernel(const int* __restrict__ x, const float* __restrict__ emb,
                             float* __restrict__ h)
{
    int row = blockIdx.x;            // 0..BSn-1
    int s   = row % Sn;
    long tok = x[row];
    const float* er = emb + tok * (long)Dn;
    float* hr = h + (long)row * Dn;
    const float c = -logf(10000.0f) / (float)Dn;
    for (int j = threadIdx.x; j < Dn; j += blockDim.x) {
        float div = expf((float)(j & ~1) * c);
        float ang = (float)s * div;
        float pe = (j & 1) ? cosf(ang) : sinf(ang);
        hr[j] = er[j] + pe;
    }
}

// ---------------- generic tiled SGEMM ----------------
// C[M,N] = alpha * A(MxK) * op(B) (+bias) (+relu)
// NT==false: B is KxN row-major (ldb).  NT==true: B is NxK row-major (ldb), C=A*B^T.
template<int BM,int BN,int BK,int TM,int TN,bool NT,bool BIAS,bool RELU>
__global__ void gemm_kernel(const float* __restrict__ A, const float* __restrict__ Bm,
                            const float* __restrict__ bias, float* __restrict__ C,
                            int M, int N, int K, int lda, int ldb, int ldc,
                            long sA, long sB, long sC, float alpha)
{
    constexpr int THREADS = (BM/TM)*(BN/TN);
    __shared__ float As[BK][BM];
    __shared__ float Bs[BK][BN];

    const int z = blockIdx.z;
    A  += z * sA;
    Bm += z * sB;
    C  += z * sC;

    const int bm = blockIdx.y * BM;
    const int bn = blockIdx.x * BN;
    const int tid = threadIdx.x;
    const int tx = tid % (BN/TN);
    const int ty = tid / (BN/TN);

    float acc[TM][TN];
#pragma unroll
    for (int i = 0; i < TM; i++)
#pragma unroll
        for (int j = 0; j < TN; j++) acc[i][j] = 0.f;

    float ra[TM], rb[TN];

    for (int k0 = 0; k0 < K; k0 += BK) {
#pragma unroll
        for (int i = tid; i < BM*BK; i += THREADS) {
            int m = i / BK, k = i % BK;
            As[k][m] = A[(long)(bm + m) * lda + k0 + k];
        }
#pragma unroll
        for (int i = tid; i < BK*BN; i += THREADS) {
            if (!NT) { int k = i / BN, n = i % BN; Bs[k][n] = Bm[(long)(k0 + k) * ldb + bn + n]; }
            else     { int n = i / BK, k = i % BK; Bs[k][n] = Bm[(long)(bn + n) * ldb + k0 + k]; }
        }
        __syncthreads();
#pragma unroll
        for (int k = 0; k < BK; k++) {
#pragma unroll
            for (int i = 0; i < TM; i++) ra[i] = As[k][ty*TM + i];
#pragma unroll
            for (int j = 0; j < TN; j++) rb[j] = Bs[k][tx*TN + j];
#pragma unroll
            for (int i = 0; i < TM; i++)
#pragma unroll
                for (int j = 0; j < TN; j++) acc[i][j] += ra[i] * rb[j];
        }
        __syncthreads();
    }

#pragma unroll
    for (int i = 0; i < TM; i++) {
        int m = bm + ty*TM + i;
#pragma unroll
        for (int j = 0; j < TN; j++) {
            int n = bn + tx*TN + j;
            float v = acc[i][j] * alpha;
            if (BIAS) v += bias[n];
            if (RELU) v = fmaxf(v, 0.f);
            C[(long)m * ldc + n] = v;
        }
    }
}

// ---------------- softmax over rows of length Sn (in place) ----------------
__global__ void softmax_kernel(float* __restrict__ p)
{
    long row = blockIdx.x;
    float* r = p + row * (long)Sn;
    const int t = threadIdx.x;                 // 256 threads, 8 elems each
    float vals[8];
    float mx = -1e30f;
#pragma unroll
    for (int i = 0; i < 8; i++) { vals[i] = r[t + i*256]; mx = fmaxf(mx, vals[i]); }

    __shared__ float red[256];
    red[t] = mx; __syncthreads();
    for (int o = 128; o > 0; o >>= 1) { if (t < o) red[t] = fmaxf(red[t], red[t+o]); __syncthreads(); }
    mx = red[0]; __syncthreads();

    float sum = 0.f;
#pragma unroll
    for (int i = 0; i < 8; i++) { vals[i] = __expf(vals[i] - mx); sum += vals[i]; }
    red[t] = sum; __syncthreads();
    for (int o = 128; o > 0; o >>= 1) { if (t < o) red[t] += red[t+o]; __syncthreads(); }
    float inv = 1.f / red[0];
#pragma unroll
    for (int i = 0; i < 8; i++) r[t + i*256] = vals[i] * inv;
}

// ---------------- residual add + LayerNorm (in place ok) ----------------
__global__ void add_ln_kernel(const float* __restrict__ x, const float* __restrict__ d,
                              const float* __restrict__ g, const float* __restrict__ bb,
                              float* __restrict__ out)
{
    int row = blockIdx.x;
    int t = threadIdx.x;                       // 256 threads, 3 elems each
    __shared__ float red[256];
    float v[3];
    float s = 0.f;
#pragma unroll
    for (int i = 0; i < 3; i++) {
        int c = t + i*256;
        v[i] = x[(long)row*Dn + c] + d[(long)row*Dn + c];
        s += v[i];
    }
    red[t] = s; __syncthreads();
    for (int o = 128; o > 0; o >>= 1) { if (t < o) red[t] += red[t+o]; __syncthreads(); }
    float mu = red[0] / (float)Dn;
    __syncthreads();
    float s2 = 0.f;
#pragma unroll
    for (int i = 0; i < 3; i++) { float dv = v[i] - mu; s2 += dv*dv; }
    red[t] = s2; __syncthreads();
    for (int o = 128; o > 0; o >>= 1) { if (t < o) red[t] += red[t+o]; __syncthreads(); }
    float inv = rsqrtf(red[0] / (float)Dn + 1e-5f);
    __syncthreads();
#pragma unroll
    for (int i = 0; i < 3; i++) {
        int c = t + i*256;
        out[(long)row*Dn + c] = (v[i] - mu) * inv * g[c] + bb[c];
    }
}

// ---------------- head reshapes ----------------
// dst[b,h,s,d] = src[b,s,h*DH+d]
__global__ void to_heads_kernel(const float* __restrict__ src, float* __restrict__ dst)
{
    long i = (long)blockIdx.x * blockDim.x + threadIdx.x;
    if (i >= (long)BSn * Dn) return;
    long b = i / ((long)Sn*Dn);
    long rem = i % ((long)Sn*Dn);
    long s = rem / Dn;
    long c = rem % Dn;
    long h = c / DHn, d = c % DHn;
    dst[(((b*Hn + h)*Sn + s)*DHn) + d] = src[i];
}
// src[b,h,s,d] -> dst[b,s,h*DH+d]
__global__ void from_heads_kernel(const float* __restrict__ src, float* __restrict__ dst)
{
    long i = (long)blockIdx.x * blockDim.x + threadIdx.x;
    if (i >= (long)BSn * Dn) return;
    long b = i / ((long)Hn*Sn*DHn);
    long rem = i % ((long)Hn*Sn*DHn);
    long h = rem / ((long)Sn*DHn);
    long r2 = rem % ((long)Sn*DHn);
    long s = r2 / DHn, d = r2 % DHn;
    dst[(b*Sn + s)*(long)Dn + h*DHn + d] = src[i];
}

// ---------------- host side ----------------
#define SYM_PTR(sym) ([]{ void* p_; cudaGetSymbolAddress(&p_, sym); return (float*)p_; }())

extern "C" void kernel_launch(void* const* d_in, const int* in_sizes, int n_in,
                              void* d_out, int out_size)
{
    const int*   x    = (const int*)  d_in[0];
    const float* emb  = (const float*)d_in[1];
    const float* Wq   = (const float*)d_in[2];
    const float* bq   = (const float*)d_in[3];
    const float* Wk   = (const float*)d_in[4];
    const float* bk   = (const float*)d_in[5];
    const float* Wv   = (const float*)d_in[6];
    const float* bv   = (const float*)d_in[7];
    const float* Wo   = (const float*)d_in[8];
    const float* bo   = (const float*)d_in[9];
    const float* ln1g = (const float*)d_in[10];
    const float* ln1b = (const float*)d_in[11];
    const float* ln2g = (const float*)d_in[12];
    const float* ln2b = (const float*)d_in[13];
    const float* W1   = (const float*)d_in[14];
    const float* b1   = (const float*)d_in[15];
    const float* W2   = (const float*)d_in[16];
    const float* b2   = (const float*)d_in[17];

    float* out = (float*)d_out;

    float* h  = SYM_PTR(g_h);
    float* q  = SYM_PTR(g_q);
    float* k  = SYM_PTR(g_k);
    float* v  = SYM_PTR(g_v);
    float* qh = SYM_PTR(g_qh);
    float* kh = SYM_PTR(g_kh);
    float* vh = SYM_PTR(g_vh);
    float* oh = SYM_PTR(g_oh);
    float* o  = SYM_PTR(g_o);
    float* t  = SYM_PTR(g_t);
    float* ff = SYM_PTR(g_ff);

    // 1) embedding + positional encoding
    embed_kernel<<<BSn, 256>>>(x, emb, h);

    const int RESHAPE_BLOCKS = (int)(((long)BSn*Dn + 255) / 256);

    for (int l = 0; l < Ln; l++) {
        const float* Wq_l = Wq + (long)l*Dn*Dn; const float* bq_l = bq + (long)l*Dn;
        const float* Wk_l = Wk + (long)l*Dn*Dn; const float* bk_l = bk + (long)l*Dn;
        const float* Wv_l = Wv + (long)l*Dn*Dn; const float* bv_l = bv + (long)l*Dn;
        const float* Wo_l = Wo + (long)l*Dn*Dn; const float* bo_l = bo + (long)l*Dn;
        const float* W1_l = W1 + (long)l*Dn*Fn; const float* b1_l = b1 + (long)l*Fn;
        const float* W2_l = W2 + (long)l*Fn*Dn; const float* b2_l = b2 + (long)l*Dn;
        float* maps = out + (long)BSn*Dn + (long)l*Bn*Hn*Sn*Sn;

        // 2) QKV projections  (M=4096, N=768, K=768)
        {
            dim3 grid(Dn/128, BSn/128, 1);
            gemm_kernel<128,128,8,8,8,false,true,false><<<grid,256>>>(
                h, Wq_l, bq_l, q, BSn, Dn, Dn, Dn, Dn, Dn, 0,0,0, 1.f);
            gemm_kernel<128,128,8,8,8,false,true,false><<<grid,256>>>(
                h, Wk_l, bk_l, k, BSn, Dn, Dn, Dn, Dn, Dn, 0,0,0, 1.f);
            gemm_kernel<128,128,8,8,8,false,true,false><<<grid,256>>>(
                h, Wv_l, bv_l, v, BSn, Dn, Dn, Dn, Dn, Dn, 0,0,0, 1.f);
        }
        // 3) split heads
        to_heads_kernel<<<RESHAPE_BLOCKS,256>>>(q, qh);
        to_heads_kernel<<<RESHAPE_BLOCKS,256>>>(k, kh);
        to_heads_kernel<<<RESHAPE_BLOCKS,256>>>(v, vh);

        // 4) scores = Q K^T / 8  -> directly into maps region (batched over B*H)
        {
            dim3 grid(Sn/128, Sn/128, BHn);
            gemm_kernel<128,128,8,8,8,true,false,false><<<grid,256>>>(
                qh, kh, nullptr, maps, Sn, Sn, DHn, DHn, DHn, Sn,
                (long)Sn*DHn, (long)Sn*DHn, (long)Sn*Sn, 0.125f);
        }
        // 5) softmax rows (in place in maps)
        softmax_kernel<<<BHn*Sn, 256>>>(maps);

        // 6) O = attn @ V   (batched, M=2048, N=64, K=2048)
        {
            dim3 grid(DHn/64, Sn/128, BHn);
            gemm_kernel<128,64,8,8,4,false,false,false><<<grid,256>>>(
                maps, vh, nullptr, oh, Sn, DHn, Sn, Sn, DHn, DHn,
                (long)Sn*Sn, (long)Sn*DHn, (long)Sn*DHn, 1.f);
        }
        // 7) merge heads
        from_heads_kernel<<<RESHAPE_BLOCKS,256>>>(oh, o);

        // 8) attn_out = o @ Wo + bo
        {
            dim3 grid(Dn/128, BSn/128, 1);
            gemm_kernel<128,128,8,8,8,false,true,false><<<grid,256>>>(
                o, Wo_l, bo_l, t, BSn, Dn, Dn, Dn, Dn, Dn, 0,0,0, 1.f);
        }
        // 9) h = LN1(h + attn_out)
        add_ln_kernel<<<BSn,256>>>(h, t, ln1g + (long)l*Dn, ln1b + (long)l*Dn, h);

        // 10) ff = relu(h @ W1 + b1)
        {
            dim3 grid(Fn/128, BSn/128, 1);
            gemm_kernel<128,128,8,8,8,false,true,true><<<grid,256>>>(
                h, W1_l, b1_l, ff, BSn, Fn, Dn, Dn, Fn, Fn, 0,0,0, 1.f);
        }
        // 11) t = ff @ W2 + b2
        {
            dim3 grid(Dn/128, BSn/128, 1);
            gemm_kernel<128,128,8,8,8,false,true,false><<<grid,256>>>(
                ff, W2_l, b2_l, t, BSn, Dn, Fn, Fn, Dn, Dn, 0,0,0, 1.f);
        }
        // 12) h = LN2(h + ff_out)
        add_ln_kernel<<<BSn,256>>>(h, t, ln2g + (long)l*Dn, ln2b + (long)l*Dn, h);
    }

    // final hidden states -> start of output
    cudaMemcpyAsync(out, h, (size_t)BSn*Dn*sizeof(float), cudaMemcpyDeviceToDevice);
}

// round 2
// speedup vs baseline: 1.8516x; 1.8516x over previous
#include <cuda_runtime.h>
#include <mma.h>
#include <math.h>

using namespace nvcuda;

// Problem constants
#define Bn 2
#define Sn 2048
#define Dn 768
#define Hn 12
#define DHn 64
#define Fn 3072
#define Ln 2
#define BSn (Bn*Sn)          // 4096
#define BHn (Bn*Hn)          // 24

// ---------------- scratch (allocation-free) ----------------
__device__ float g_h [BSn*Dn];
__device__ float g_q [BSn*Dn];
__device__ float g_k [BSn*Dn];
__device__ float g_v [BSn*Dn];
__device__ float g_qh[BSn*Dn];
__device__ float g_kh[BSn*Dn];
__device__ float g_vh[BSn*Dn];
__device__ float g_oh[BSn*Dn];
__device__ float g_o [BSn*Dn];
__device__ float g_t [BSn*Dn];
__device__ float g_ff[BSn*Fn];

// ---------------- embedding + sinusoidal PE ----------------
__global__ void embed_kernel(const int* __restrict__ x, const float* __restrict__ emb,
                             float* __restrict__ h)
{
    int row = blockIdx.x;            // 0..BSn-1
    int s   = row % Sn;
    long tok = x[row];
    const float* er = emb + tok * (long)Dn;
    float* hr = h + (long)row * Dn;
    const float c = -logf(10000.0f) / (float)Dn;
    for (int j = threadIdx.x; j < Dn; j += blockDim.x) {
        float div = expf((float)(j & ~1) * c);
        float ang = (float)s * div;
        float pe = (j & 1) ? cosf(ang) : sinf(ang);
        hr[j] = er[j] + pe;
    }
}

// ---------------- TF32 tensor-core GEMM ----------------
// C[M,N] = alpha * A(MxK) * op(B)
// NT==false: B is KxN row-major (ldb).  NT==true: B is NxK row-major (ldb), C=A*B^T.
// Tiles: BM x BN x 32, 256 threads (8 warps), warp grid 4x2, fragments 16x16x8 tf32.
template<int BM, int BN, bool NT>
__global__ __launch_bounds__(256)
void gemm_tc_kernel(const float* __restrict__ A, const float* __restrict__ Bm,
                    float* __restrict__ C,
                    int M, int N, int K, int lda, int ldb, int ldc,
                    long sA, long sB, long sC, float alpha)
{
    constexpr int BK = 32;
    constexpr int WARPS_M = 4, WARPS_N = 2;
    constexpr int WM = BM / WARPS_M;         // rows per warp
    constexpr int WN = BN / WARPS_N;         // cols per warp
    constexpr int FM = WM / 16;              // a-fragments per warp
    constexpr int FN = WN / 16;              // b-fragments per warp
    constexpr int LDA_S = BK + 8;            // 40 (mult of 4, conflict-avoiding)
    constexpr int LDB_S = BN + 8;            // 136 / 72

    __shared__ float As[BM][LDA_S];
    __shared__ float Bs[BK][LDB_S];

    const int z = blockIdx.z;
    A  += z * sA;
    Bm += z * sB;
    C  += z * sC;

    const int bm = blockIdx.y * BM;
    const int bn = blockIdx.x * BN;
    const int tid = threadIdx.x;
    const int warp = tid >> 5;
    const int wm = (warp % WARPS_M) * WM;
    const int wn = (warp / WARPS_M) * WN;

    wmma::fragment<wmma::accumulator, 16, 16, 8, float> acc[FM][FN];
#pragma unroll
    for (int i = 0; i < FM; i++)
#pragma unroll
        for (int j = 0; j < FN; j++) wmma::fill_fragment(acc[i][j], 0.0f);

    for (int k0 = 0; k0 < K; k0 += BK) {
        // --- stage A: BM x 32, float4 along k ---
        {
            const int row0 = tid >> 3;            // 32 rows per pass
            const int kv   = (tid & 7) * 4;
#pragma unroll
            for (int p = 0; p < BM / 32; p++) {
                int m = row0 + p * 32;
                float4 va = *(const float4*)(A + (long)(bm + m) * lda + k0 + kv);
                As[m][kv + 0] = va.x; As[m][kv + 1] = va.y;
                As[m][kv + 2] = va.z; As[m][kv + 3] = va.w;
            }
        }
        // --- stage B ---
        if (!NT) {
            // B tile: 32 x BN, row-major source
            const int row0 = tid / (BN / 4);
            const int nv   = (tid % (BN / 4)) * 4;
            constexpr int RP = 256 / (BN / 4);     // rows per pass
#pragma unroll
            for (int p = 0; p < BK / RP; p++) {
                int k = row0 + p * RP;
                float4 vb = *(const float4*)(Bm + (long)(k0 + k) * ldb + bn + nv);
                Bs[k][nv + 0] = vb.x; Bs[k][nv + 1] = vb.y;
                Bs[k][nv + 2] = vb.z; Bs[k][nv + 3] = vb.w;
            }
        } else {
            // B is NxK row-major; Bs[k][n] = B[bn+n][k0+k]
            const int n0 = tid >> 3;              // 32 n per pass
            const int kv = (tid & 7) * 4;
#pragma unroll
            for (int p = 0; p < BN / 32; p++) {
                int n = n0 + p * 32;
                float4 vb = *(const float4*)(Bm + (long)(bn + n) * ldb + k0 + kv);
                Bs[kv + 0][n] = vb.x; Bs[kv + 1][n] = vb.y;
                Bs[kv + 2][n] = vb.z; Bs[kv + 3][n] = vb.w;
            }
        }
        __syncthreads();

#pragma unroll
        for (int kf = 0; kf < BK / 8; kf++) {
            wmma::fragment<wmma::matrix_a, 16, 16, 8, wmma::precision::tf32, wmma::row_major> af[FM];
            wmma::fragment<wmma::matrix_b, 16, 16, 8, wmma::precision::tf32, wmma::row_major> bf[FN];
#pragma unroll
            for (int i = 0; i < FM; i++) {
                wmma::load_matrix_sync(af[i], &As[wm + i * 16][kf * 8], LDA_S);
#pragma unroll
                for (int e = 0; e < af[i].num_elements; e++)
                    af[i].x[e] = wmma::__float_to_tf32(af[i].x[e]);
            }
#pragma unroll
            for (int j = 0; j < FN; j++) {
                wmma::load_matrix_sync(bf[j], &Bs[kf * 8][wn + j * 16], LDB_S);
#pragma unroll
                for (int e = 0; e < bf[j].num_elements; e++)
                    bf[j].x[e] = wmma::__float_to_tf32(bf[j].x[e]);
            }
#pragma unroll
            for (int i = 0; i < FM; i++)
#pragma unroll
                for (int j = 0; j < FN; j++)
                    wmma::mma_sync(acc[i][j], af[i], bf[j], acc[i][j]);
        }
        __syncthreads();
    }

    // epilogue: scale + direct store
    if (alpha != 1.0f) {
#pragma unroll
        for (int i = 0; i < FM; i++)
#pragma unroll
            for (int j = 0; j < FN; j++)
#pragma unroll
                for (int e = 0; e < acc[i][j].num_elements; e++)
                    acc[i][j].x[e] *= alpha;
    }
#pragma unroll
    for (int i = 0; i < FM; i++)
#pragma unroll
        for (int j = 0; j < FN; j++)
            wmma::store_matrix_sync(C + (long)(bm + wm + i * 16) * ldc + bn + wn + j * 16,
                                    acc[i][j], ldc, wmma::mem_row_major);
}

// ---------------- bias (+optional relu) elementwise ----------------
template<bool RELU>
__global__ void bias_kernel(float* __restrict__ C, const float* __restrict__ bias,
                            long total, int N)
{
    long i = (long)blockIdx.x * blockDim.x + threadIdx.x;
    if (i >= total) return;
    float v = C[i] + bias[i % N];
    if (RELU) v = fmaxf(v, 0.f);
    C[i] = v;
}

// ---------------- softmax over rows of length Sn (in place) ----------------
__global__ void softmax_kernel(float* __restrict__ p)
{
    long row = blockIdx.x;
    float* r = p + row * (long)Sn;
    const int t = threadIdx.x;                 // 256 threads, 8 elems each
    float vals[8];
    float mx = -1e30f;
#pragma unroll
    for (int i = 0; i < 8; i++) { vals[i] = r[t + i*256]; mx = fmaxf(mx, vals[i]); }

    __shared__ float red[256];
    red[t] = mx; __syncthreads();
    for (int o = 128; o > 0; o >>= 1) { if (t < o) red[t] = fmaxf(red[t], red[t+o]); __syncthreads(); }
    mx = red[0]; __syncthreads();

    float sum = 0.f;
#pragma unroll
    for (int i = 0; i < 8; i++) { vals[i] = __expf(vals[i] - mx); sum += vals[i]; }
    red[t] = sum; __syncthreads();
    for (int o = 128; o > 0; o >>= 1) { if (t < o) red[t] += red[t+o]; __syncthreads(); }
    float inv = 1.f / red[0];
#pragma unroll
    for (int i = 0; i < 8; i++) r[t + i*256] = vals[i] * inv;
}

// ---------------- residual add + LayerNorm (in place ok) ----------------
__global__ void add_ln_kernel(const float* __restrict__ x, const float* __restrict__ d,
                              const float* __restrict__ g, const float* __restrict__ bb,
                              float* __restrict__ out)
{
    int row = blockIdx.x;
    int t = threadIdx.x;                       // 256 threads, 3 elems each
    __shared__ float red[256];
    float v[3];
    float s = 0.f;
#pragma unroll
    for (int i = 0; i < 3; i++) {
        int c = t + i*256;
        v[i] = x[(long)row*Dn + c] + d[(long)row*Dn + c];
        s += v[i];
    }
    red[t] = s; __syncthreads();
    for (int o = 128; o > 0; o >>= 1) { if (t < o) red[t] += red[t+o]; __syncthreads(); }
    float mu = red[0] / (float)Dn;
    __syncthreads();
    float s2 = 0.f;
#pragma unroll
    for (int i = 0; i < 3; i++) { float dv = v[i] - mu; s2 += dv*dv; }
    red[t] = s2; __syncthreads();
    for (int o = 128; o > 0; o >>= 1) { if (t < o) red[t] += red[t+o]; __syncthreads(); }
    float inv = rsqrtf(red[0] / (float)Dn + 1e-5f);
    __syncthreads();
#pragma unroll
    for (int i = 0; i < 3; i++) {
        int c = t + i*256;
        out[(long)row*Dn + c] = (v[i] - mu) * inv * g[c] + bb[c];
    }
}

// ---------------- head reshapes ----------------
__global__ void to_heads_kernel(const float* __restrict__ src, float* __restrict__ dst)
{
    long i = (long)blockIdx.x * blockDim.x + threadIdx.x;
    if (i >= (long)BSn * Dn) return;
    long b = i / ((long)Sn*Dn);
    long rem = i % ((long)Sn*Dn);
    long s = rem / Dn;
    long c = rem % Dn;
    long h = c / DHn, d = c % DHn;
    dst[(((b*Hn + h)*Sn + s)*DHn) + d] = src[i];
}
__global__ void from_heads_kernel(const float* __restrict__ src, float* __restrict__ dst)
{
    long i = (long)blockIdx.x * blockDim.x + threadIdx.x;
    if (i >= (long)BSn * Dn) return;
    long b = i / ((long)Hn*Sn*DHn);
    long rem = i % ((long)Hn*Sn*DHn);
    long h = rem / ((long)Sn*DHn);
    long r2 = rem % ((long)Sn*DHn);
    long s = r2 / DHn, d = r2 % DHn;
    dst[(b*Sn + s)*(long)Dn + h*DHn + d] = src[i];
}

// ---------------- host side ----------------
#define SYM_PTR(sym) ([]{ void* p_; cudaGetSymbolAddress(&p_, sym); return (float*)p_; }())

static inline void bias_add(float* C, const float* b, long M, int N, bool relu) {
    long total = M * (long)N;
    int blocks = (int)((total + 255) / 256);
    if (relu) bias_kernel<true><<<blocks, 256>>>(C, b, total, N);
    else      bias_kernel<false><<<blocks, 256>>>(C, b, total, N);
}

extern "C" void kernel_launch(void* const* d_in, const int* in_sizes, int n_in,
                              void* d_out, int out_size)
{
    const int*   x    = (const int*)  d_in[0];
    const float* emb  = (const float*)d_in[1];
    const float* Wq   = (const float*)d_in[2];
    const float* bq   = (const float*)d_in[3];
    const float* Wk   = (const float*)d_in[4];
    const float* bk   = (const float*)d_in[5];
    const float* Wv   = (const float*)d_in[6];
    const float* bv   = (const float*)d_in[7];
    const float* Wo   = (const float*)d_in[8];
    const float* bo   = (const float*)d_in[9];
    const float* ln1g = (const float*)d_in[10];
    const float* ln1b = (const float*)d_in[11];
    const float* ln2g = (const float*)d_in[12];
    const float* ln2b = (const float*)d_in[13];
    const float* W1   = (const float*)d_in[14];
    const float* b1   = (const float*)d_in[15];
    const float* W2   = (const float*)d_in[16];
    const float* b2   = (const float*)d_in[17];

    float* out = (float*)d_out;

    float* h  = SYM_PTR(g_h);
    float* q  = SYM_PTR(g_q);
    float* k  = SYM_PTR(g_k);
    float* v  = SYM_PTR(g_v);
    float* qh = SYM_PTR(g_qh);
    float* kh = SYM_PTR(g_kh);
    float* vh = SYM_PTR(g_vh);
    float* oh = SYM_PTR(g_oh);
    float* o  = SYM_PTR(g_o);
    float* t  = SYM_PTR(g_t);
    float* ff = SYM_PTR(g_ff);

    // 1) embedding + positional encoding
    embed_kernel<<<BSn, 256>>>(x, emb, h);

    const int RESHAPE_BLOCKS = (int)(((long)BSn*Dn + 255) / 256);

    for (int l = 0; l < Ln; l++) {
        const float* Wq_l = Wq + (long)l*Dn*Dn; const float* bq_l = bq + (long)l*Dn;
        const float* Wk_l = Wk + (long)l*Dn*Dn; const float* bk_l = bk + (long)l*Dn;
        const float* Wv_l = Wv + (long)l*Dn*Dn; const float* bv_l = bv + (long)l*Dn;
        const float* Wo_l = Wo + (long)l*Dn*Dn; const float* bo_l = bo + (long)l*Dn;
        const float* W1_l = W1 + (long)l*Dn*Fn; const float* b1_l = b1 + (long)l*Fn;
        const float* W2_l = W2 + (long)l*Fn*Dn; const float* b2_l = b2 + (long)l*Dn;
        float* maps = out + (long)BSn*Dn + (long)l*Bn*Hn*Sn*Sn;

        // 2) QKV projections  (M=4096, N=768, K=768)
        {
            dim3 grid(Dn/128, BSn/128, 1);
            gemm_tc_kernel<128,128,false><<<grid,256>>>(h, Wq_l, q, BSn, Dn, Dn, Dn, Dn, Dn, 0,0,0, 1.f);
            gemm_tc_kernel<128,128,false><<<grid,256>>>(h, Wk_l, k, BSn, Dn, Dn, Dn, Dn, Dn, 0,0,0, 1.f);
            gemm_tc_kernel<128,128,false><<<grid,256>>>(h, Wv_l, v, BSn, Dn, Dn, Dn, Dn, Dn, 0,0,0, 1.f);
            bias_add(q, bq_l, BSn, Dn, false);
            bias_add(k, bk_l, BSn, Dn, false);
            bias_add(v, bv_l, BSn, Dn, false);
        }
        // 3) split heads
        to_heads_kernel<<<RESHAPE_BLOCKS,256>>>(q, qh);
        to_heads_kernel<<<RESHAPE_BLOCKS,256>>>(k, kh);
        to_heads_kernel<<<RESHAPE_BLOCKS,256>>>(v, vh);

        // 4) scores = Q K^T / 8  -> directly into maps region (batched over B*H)
        {
            dim3 grid(Sn/128, Sn/128, BHn);
            gemm_tc_kernel<128,128,true><<<grid,256>>>(
                qh, kh, maps, Sn, Sn, DHn, DHn, DHn, Sn,
                (long)Sn*DHn, (long)Sn*DHn, (long)Sn*Sn, 0.125f);
        }
        // 5) softmax rows (in place in maps)
        softmax_kernel<<<BHn*Sn, 256>>>(maps);

        // 6) O = attn @ V   (batched, M=2048, N=64, K=2048)
        {
            dim3 grid(1, Sn/128, BHn);
            gemm_tc_kernel<128,64,false><<<grid,256>>>(
                maps, vh, oh, Sn, DHn, Sn, Sn, DHn, DHn,
                (long)Sn*Sn, (long)Sn*DHn, (long)Sn*DHn, 1.f);
        }
        // 7) merge heads
        from_heads_kernel<<<RESHAPE_BLOCKS,256>>>(oh, o);

        // 8) attn_out = o @ Wo + bo
        {
            dim3 grid(Dn/128, BSn/128, 1);
            gemm_tc_kernel<128,128,false><<<grid,256>>>(o, Wo_l, t, BSn, Dn, Dn, Dn, Dn, Dn, 0,0,0, 1.f);
            bias_add(t, bo_l, BSn, Dn, false);
        }
        // 9) h = LN1(h + attn_out)
        add_ln_kernel<<<BSn,256>>>(h, t, ln1g + (long)l*Dn, ln1b + (long)l*Dn, h);

        // 10) ff = relu(h @ W1 + b1)
        {
            dim3 grid(Fn/128, BSn/128, 1);
            gemm_tc_kernel<128,128,false><<<grid,256>>>(h, W1_l, ff, BSn, Fn, Dn, Dn, Fn, Fn, 0,0,0, 1.f);
            bias_add(ff, b1_l, BSn, Fn, true);
        }
        // 11) t = ff @ W2 + b2
        {
            dim3 grid(Dn/128, BSn/128, 1);
            gemm_tc_kernel<128,128,false><<<grid,256>>>(ff, W2_l, t, BSn, Dn, Fn, Fn, Dn, Dn, 0,0,0, 1.f);
            bias_add(t, b2_l, BSn, Dn, false);
        }
        // 12) h = LN2(h + ff_out)
        add_ln_kernel<<<BSn,256>>>(h, t, ln2g + (long)l*Dn, ln2b + (long)l*Dn, h);
    }

    // final hidden states -> start of output
    cudaMemcpyAsync(out, h, (size_t)BSn*Dn*sizeof(float), cudaMemcpyDeviceToDevice);
}

// round 4
// speedup vs baseline: 2.1328x; 1.1519x over previous
#include <cuda_runtime.h>
#include <mma.h>
#include <math.h>
#include <cstdint>
#include <stdint.h>

using namespace nvcuda;

#define Bn 2
#define Sn 2048
#define Dn 768
#define Hn 12
#define DHn 64
#define Fn 3072
#define Ln 2
#define BSn (Bn*Sn)
#define BHn (Bn*Hn)

// ---------------- scratch ----------------
__device__ float g_h [BSn*Dn];
__device__ float g_qh[BSn*Dn];
__device__ float g_kh[BSn*Dn];
__device__ float g_vh[BSn*Dn];
__device__ float g_o [BSn*Dn];
__device__ float g_t [BSn*Dn];
__device__ float g_ff[BSn*Fn];

// ---------------- cp.async helpers ----------------
__device__ __forceinline__ void cp_async16(uint32_t saddr, const void* gaddr) {
    asm volatile("cp.async.cg.shared.global [%0], [%1], 16;\n" :: "r"(saddr), "l"(gaddr));
}
#define CP_COMMIT() asm volatile("cp.async.commit_group;\n" ::)
#define CP_WAIT1()  asm volatile("cp.async.wait_group 1;\n" ::)
#define CP_WAIT0()  asm volatile("cp.async.wait_group 0;\n" ::)

// ---------------- embedding + sinusoidal PE ----------------
__global__ void embed_kernel(const int* __restrict__ x, const float* __restrict__ emb,
                             float* __restrict__ h)
{
    int row = blockIdx.x;
    int s   = row % Sn;
    long tok = x[row];
    const float* er = emb + tok * (long)Dn;
    float* hr = h + (long)row * Dn;
    const float c = -logf(10000.0f) / (float)Dn;
    for (int j = threadIdx.x; j < Dn; j += blockDim.x) {
        float div = expf((float)(j & ~1) * c);
        float ang = (float)s * div;
        float pe = (j & 1) ? cosf(ang) : sinf(ang);
        hr[j] = er[j] + pe;
    }
}

// ---------------- pipelined TF32 tensor-core GEMM ----------------
// MODE: 0 = plain C[m*ldc+n], 1 = heads (QKV -> [b,h,s,d]), 2 = merge (AV -> [b,s,D])
// MULTI: blockIdx.z selects among {B0,B1,B2}/{bias0..}/{C0..} (shared A); else batch strides.
template<int BM, int BN, bool NT, int MODE, bool MULTI>
__global__ __launch_bounds__(256)
void gemm_tc(const float* __restrict__ A,
             const float* B0, const float* B1, const float* B2,
             const float* bias0, const float* bias1, const float* bias2,
             float* C0, float* C1, float* C2,
             int M, int N, int K, int lda, int ldb, int ldc,
             long sA, long sB, long sC, float alpha, int relu)
{
    constexpr int BK = 32;
    constexpr int STAGES = 3;
    constexpr int LDA_S = BK + 4;                 // 36
    constexpr int LDB_S = NT ? (BK + 4) : (BN + 4);
    constexpr int BROWS = NT ? BN : BK;           // rows of B stage buffer
    constexpr int LDC_S = BN + 4;
    constexpr int WARPS_M = 4, WARPS_N = 2;
    constexpr int WM = BM / WARPS_M;
    constexpr int WN = BN / WARPS_N;
    constexpr int FM = WM / 16;
    constexpr int FN = WN / 16;

    extern __shared__ char smem_raw[];
    float* As = (float*)smem_raw;                       // [STAGES][BM][LDA_S]
    float* Bs = As + STAGES * BM * LDA_S;               // [STAGES][BROWS][LDB_S]
    float* Cs = (float*)smem_raw;                       // epilogue alias [BM][LDC_S]

    const int z = blockIdx.z;
    const float* Bm; const float* bias; float* C;
    if (MULTI) {
        Bm   = (z == 0) ? B0 : ((z == 1) ? B1 : B2);
        bias = (z == 0) ? bias0 : ((z == 1) ? bias1 : bias2);
        C    = (z == 0) ? C0 : ((z == 1) ? C1 : C2);
    } else {
        Bm   = B0 + z * sB;
        bias = bias0;
        C    = C0 + z * sC;
        A   += z * sA;
    }

    const int bm = blockIdx.y * BM;
    const int bn = blockIdx.x * BN;
    const int tid = threadIdx.x;
    const int warp = tid >> 5;
    const int wm = (warp % WARPS_M) * WM;
    const int wn = (warp / WARPS_M) * WN;

    const uint32_t sAs = (uint32_t)__cvta_generic_to_shared(As);
    const uint32_t sBs = (uint32_t)__cvta_generic_to_shared(Bs);

    wmma::fragment<wmma::accumulator, 16, 16, 8, float> acc[FM][FN];
#pragma unroll
    for (int i = 0; i < FM; i++)
#pragma unroll
        for (int j = 0; j < FN; j++) wmma::fill_fragment(acc[i][j], 0.0f);

    const int kIters = K / BK;

    auto load_stage = [&](int st, int ki) {
        if (ki >= kIters) return;
        const int k0 = ki * BK;
        // A tile: BM x BK
        constexpr int NVA = BM * BK / 4;
#pragma unroll
        for (int e = tid; e < NVA; e += 256) {
            int m  = e / (BK / 4);
            int kv = (e % (BK / 4)) * 4;
            cp_async16(sAs + ((st * BM + m) * LDA_S + kv) * 4,
                       A + (long)(bm + m) * lda + k0 + kv);
        }
        if (!NT) {
            // B tile: BK x BN (row-major src)
            constexpr int NVB = BK * BN / 4;
#pragma unroll
            for (int e = tid; e < NVB; e += 256) {
                int k  = e / (BN / 4);
                int nv = (e % (BN / 4)) * 4;
                cp_async16(sBs + ((st * BROWS + k) * LDB_S + nv) * 4,
                           Bm + (long)(k0 + k) * ldb + bn + nv);
            }
        } else {
            // B is NxK row-major; stage as BsT[n][k]
            constexpr int NVB = BN * BK / 4;
#pragma unroll
            for (int e = tid; e < NVB; e += 256) {
                int n  = e / (BK / 4);
                int kv = (e % (BK / 4)) * 4;
                cp_async16(sBs + ((st * BROWS + n) * LDB_S + kv) * 4,
                           Bm + (long)(bn + n) * ldb + k0 + kv);
            }
        }
    };

    // prefetch
    for (int s = 0; s < STAGES - 1; s++) { load_stage(s, s); CP_COMMIT(); }

    for (int ki = 0; ki < kIters; ki++) {
        CP_WAIT1();
        __syncthreads();
        load_stage((ki + STAGES - 1) % STAGES, ki + STAGES - 1);
        CP_COMMIT();

        const int st = ki % STAGES;
        const float* Ast = As + st * BM * LDA_S;
        const float* Bst = Bs + st * BROWS * LDB_S;
#pragma unroll
        for (int kf = 0; kf < BK / 8; kf++) {
            wmma::fragment<wmma::matrix_a, 16, 16, 8, wmma::precision::tf32, wmma::row_major> af[FM];
#pragma unroll
            for (int i = 0; i < FM; i++) {
                wmma::load_matrix_sync(af[i], Ast + (wm + i * 16) * LDA_S + kf * 8, LDA_S);
#pragma unroll
                for (int e = 0; e < af[i].num_elements; e++)
                    af[i].x[e] = wmma::__float_to_tf32(af[i].x[e]);
            }
            if (!NT) {
                wmma::fragment<wmma::matrix_b, 16, 16, 8, wmma::precision::tf32, wmma::row_major> bf[FN];
#pragma unroll
                for (int j = 0; j < FN; j++) {
                    wmma::load_matrix_sync(bf[j], Bst + (kf * 8) * LDB_S + wn + j * 16, LDB_S);
#pragma unroll
                    for (int e = 0; e < bf[j].num_elements; e++)
                        bf[j].x[e] = wmma::__float_to_tf32(bf[j].x[e]);
                }
#pragma unroll
                for (int i = 0; i < FM; i++)
#pragma unroll
                    for (int j = 0; j < FN; j++)
                        wmma::mma_sync(acc[i][j], af[i], bf[j], acc[i][j]);
            } else {
                wmma::fragment<wmma::matrix_b, 16, 16, 8, wmma::precision::tf32, wmma::col_major> bf[FN];
#pragma unroll
                for (int j = 0; j < FN; j++) {
                    wmma::load_matrix_sync(bf[j], Bst + (wn + j * 16) * LDB_S + kf * 8, LDB_S);
#pragma unroll
                    for (int e = 0; e < bf[j].num_elements; e++)
                        bf[j].x[e] = wmma::__float_to_tf32(bf[j].x[e]);
                }
#pragma unroll
                for (int i = 0; i < FM; i++)
#pragma unroll
                    for (int j = 0; j < FN; j++)
                        wmma::mma_sync(acc[i][j], af[i], bf[j], acc[i][j]);
            }
        }
    }

    CP_WAIT0();
    __syncthreads();   // pipeline done; reuse smem for epilogue

#pragma unroll
    for (int i = 0; i < FM; i++)
#pragma unroll
        for (int j = 0; j < FN; j++)
            wmma::store_matrix_sync(Cs + (wm + i * 16) * LDC_S + wn + j * 16,
                                    acc[i][j], LDC_S, wmma::mem_row_major);
    __syncthreads();

    // fused epilogue: alpha, bias, relu, layout-transforming store
    constexpr int NVC = BM * BN / 4;
#pragma unroll 4
    for (int e = tid; e < NVC; e += 256) {
        int m  = e / (BN / 4);
        int nv = (e % (BN / 4)) * 4;
        float4 v = *(const float4*)&Cs[m * LDC_S + nv];
        if (alpha != 1.0f) { v.x *= alpha; v.y *= alpha; v.z *= alpha; v.w *= alpha; }
        if (bias) {
            int c = bn + nv;
            v.x += bias[c]; v.y += bias[c + 1]; v.z += bias[c + 2]; v.w += bias[c + 3];
        }
        if (relu) {
            v.x = fmaxf(v.x, 0.f); v.y = fmaxf(v.y, 0.f);
            v.z = fmaxf(v.z, 0.f); v.w = fmaxf(v.w, 0.f);
        }
        if (MODE == 0) {
            *(float4*)&C[(long)(bm + m) * ldc + bn + nv] = v;
        } else if (MODE == 1) {
            int r = bm + m, c = bn + nv;
            int b = r >> 11, s = r & (Sn - 1);
            int hh = c >> 6, d = c & 63;
            *(float4*)&C[((((long)b * Hn + hh) * Sn + s) << 6) + d] = v;
        } else {
            int b = z / Hn, hh = z % Hn;
            *(float4*)&C[((long)(b * Sn + bm + m)) * Dn + hh * DHn + bn + nv] = v;
        }
    }
}

// ---------------- softmax over rows of length Sn (in place) ----------------
__global__ void softmax_kernel(float* __restrict__ p)
{
    long row = blockIdx.x;
    float* r = p + row * (long)Sn;
    const int t = threadIdx.x;
    float vals[8];
    float mx = -1e30f;
#pragma unroll
    for (int i = 0; i < 8; i++) { vals[i] = r[t + i*256]; mx = fmaxf(mx, vals[i]); }

    __shared__ float red[256];
    red[t] = mx; __syncthreads();
    for (int o = 128; o > 0; o >>= 1) { if (t < o) red[t] = fmaxf(red[t], red[t+o]); __syncthreads(); }
    mx = red[0]; __syncthreads();

    float sum = 0.f;
#pragma unroll
    for (int i = 0; i < 8; i++) { vals[i] = __expf(vals[i] - mx); sum += vals[i]; }
    red[t] = sum; __syncthreads();
    for (int o = 128; o > 0; o >>= 1) { if (t < o) red[t] += red[t+o]; __syncthreads(); }
    float inv = 1.f / red[0];
#pragma unroll
    for (int i = 0; i < 8; i++) r[t + i*256] = vals[i] * inv;
}

// ---------------- residual add + LayerNorm ----------------
__global__ void add_ln_kernel(const float* __restrict__ x, const float* __restrict__ d,
                              const float* __restrict__ g, const float* __restrict__ bb,
                              float* __restrict__ out)
{
    int row = blockIdx.x;
    int t = threadIdx.x;
    __shared__ float red[256];
    float v[3];
    float s = 0.f;
#pragma unroll
    for (int i = 0; i < 3; i++) {
        int c = t + i*256;
        v[i] = x[(long)row*Dn + c] + d[(long)row*Dn + c];
        s += v[i];
    }
    red[t] = s; __syncthreads();
    for (int o = 128; o > 0; o >>= 1) { if (t < o) red[t] += red[t+o]; __syncthreads(); }
    float mu = red[0] / (float)Dn;
    __syncthreads();
    float s2 = 0.f;
#pragma unroll
    for (int i = 0; i < 3; i++) { float dv = v[i] - mu; s2 += dv*dv; }
    red[t] = s2; __syncthreads();
    for (int o = 128; o > 0; o >>= 1) { if (t < o) red[t] += red[t+o]; __syncthreads(); }
    float inv = rsqrtf(red[0] / (float)Dn + 1e-5f);
    __syncthreads();
#pragma unroll
    for (int i = 0; i < 3; i++) {
        int c = t + i*256;
        out[(long)row*Dn + c] = (v[i] - mu) * inv * g[c] + bb[c];
    }
}

// ---------------- host side ----------------
#define SYM_PTR(sym) ([]{ void* p_; cudaGetSymbolAddress(&p_, sym); return (float*)p_; }())

// smem sizes (bytes)
#define SMEM_NN128 ((3*(128*36 + 32*132))*4)   // 105984
#define SMEM_NT128 ((3*(128*36 + 128*36))*4)   // 110592
#define SMEM_NN64  ((3*(128*36 + 32*68))*4)    // 81408

extern "C" void kernel_launch(void* const* d_in, const int* in_sizes, int n_in,
                              void* d_out, int out_size)
{
    const int*   x    = (const int*)  d_in[0];
    const float* emb  = (const float*)d_in[1];
    const float* Wq   = (const float*)d_in[2];
    const float* bq   = (const float*)d_in[3];
    const float* Wk   = (const float*)d_in[4];
    const float* bk   = (const float*)d_in[5];
    const float* Wv   = (const float*)d_in[6];
    const float* bv   = (const float*)d_in[7];
    const float* Wo   = (const float*)d_in[8];
    const float* bo   = (const float*)d_in[9];
    const float* ln1g = (const float*)d_in[10];
    const float* ln1b = (const float*)d_in[11];
    const float* ln2g = (const float*)d_in[12];
    const float* ln2b = (const float*)d_in[13];
    const float* W1   = (const float*)d_in[14];
    const float* b1   = (const float*)d_in[15];
    const float* W2   = (const float*)d_in[16];
    const float* b2   = (const float*)d_in[17];

    float* out = (float*)d_out;

    float* h  = SYM_PTR(g_h);
    float* qh = SYM_PTR(g_qh);
    float* kh = SYM_PTR(g_kh);
    float* vh = SYM_PTR(g_vh);
    float* o  = SYM_PTR(g_o);
    float* t  = SYM_PTR(g_t);
    float* ff = SYM_PTR(g_ff);

    // raise smem limits (idempotent)
    cudaFuncSetAttribute(gemm_tc<128,128,false,1,true>,  cudaFuncAttributeMaxDynamicSharedMemorySize, SMEM_NN128);
    cudaFuncSetAttribute(gemm_tc<128,128,false,0,false>, cudaFuncAttributeMaxDynamicSharedMemorySize, SMEM_NN128);
    cudaFuncSetAttribute(gemm_tc<128,128,true, 0,false>, cudaFuncAttributeMaxDynamicSharedMemorySize, SMEM_NT128);
    cudaFuncSetAttribute(gemm_tc<128,64, false,2,false>, cudaFuncAttributeMaxDynamicSharedMemorySize, SMEM_NN64);

    embed_kernel<<<BSn, 256>>>(x, emb, h);

    for (int l = 0; l < Ln; l++) {
        const float* Wq_l = Wq + (long)l*Dn*Dn; const float* bq_l = bq + (long)l*Dn;
        const float* Wk_l = Wk + (long)l*Dn*Dn; const float* bk_l = bk + (long)l*Dn;
        const float* Wv_l = Wv + (long)l*Dn*Dn; const float* bv_l = bv + (long)l*Dn;
        const float* Wo_l = Wo + (long)l*Dn*Dn; const float* bo_l = bo + (long)l*Dn;
        const float* W1_l = W1 + (long)l*Dn*Fn; const float* b1_l = b1 + (long)l*Fn;
        const float* W2_l = W2 + (long)l*Fn*Dn; const float* b2_l = b2 + (long)l*Dn;
        float* maps = out + (long)BSn*Dn + (long)l*Bn*Hn*Sn*Sn;

        // QKV fused: one launch, z selects q/k/v; writes head layout directly
        {
            dim3 grid(Dn/128, BSn/128, 3);
            gemm_tc<128,128,false,1,true><<<grid,256,SMEM_NN128>>>(
                h, Wq_l, Wk_l, Wv_l, bq_l, bk_l, bv_l, qh, kh, vh,
                BSn, Dn, Dn, Dn, Dn, 0, 0,0,0, 1.f, 0);
        }
        // scores = Q K^T / 8 -> maps (batched over B*H)
        {
            dim3 grid(Sn/128, Sn/128, BHn);
            gemm_tc<128,128,true,0,false><<<grid,256,SMEM_NT128>>>(
                qh, kh, nullptr, nullptr, nullptr, nullptr, nullptr,
                maps, nullptr, nullptr,
                Sn, Sn, DHn, DHn, DHn, Sn,
                (long)Sn*DHn, (long)Sn*DHn, (long)Sn*Sn, 0.125f, 0);
        }
        softmax_kernel<<<BHn*Sn, 256>>>(maps);
        // O = attn @ V -> merged layout directly
        {
            dim3 grid(1, Sn/128, BHn);
            gemm_tc<128,64,false,2,false><<<grid,256,SMEM_NN64>>>(
                maps, vh, nullptr, nullptr, nullptr, nullptr, nullptr,
                o, nullptr, nullptr,
                Sn, DHn, Sn, Sn, DHn, 0,
                (long)Sn*Sn, (long)Sn*DHn, 0, 1.f, 0);
        }
        // attn_out = o @ Wo + bo
        {
            dim3 grid(Dn/128, BSn/128, 1);
            gemm_tc<128,128,false,0,false><<<grid,256,SMEM_NN128>>>(
                o, Wo_l, nullptr, nullptr, bo_l, nullptr, nullptr,
                t, nullptr, nullptr,
                BSn, Dn, Dn, Dn, Dn, Dn, 0,0,0, 1.f, 0);
        }
        add_ln_kernel<<<BSn,256>>>(h, t, ln1g + (long)l*Dn, ln1b + (long)l*Dn, h);
        // ff = relu(h @ W1 + b1)
        {
            dim3 grid(Fn/128, BSn/128, 1);
            gemm_tc<128,128,false,0,false><<<grid,256,SMEM_NN128>>>(
                h, W1_l, nullptr, nullptr, b1_l, nullptr, nullptr,
                ff, nullptr, nullptr,
                BSn, Fn, Dn, Dn, Fn, Fn, 0,0,0, 1.f, 1);
        }
        // t = ff @ W2 + b2
        {
            dim3 grid(Dn/128, BSn/128, 1);
            gemm_tc<128,128,false,0,false><<<grid,256,SMEM_NN128>>>(
                ff, W2_l, nullptr, nullptr, b2_l, nullptr, nullptr,
                t, nullptr, nullptr,
                BSn, Dn, Fn, Fn, Dn, Dn, 0,0,0, 1.f, 0);
        }
        add_ln_kernel<<<BSn,256>>>(h, t, ln2g + (long)l*Dn, ln2b + (long)l*Dn, h);
    }

    cudaMemcpyAsync(out, h, (size_t)BSn*Dn*sizeof(float), cudaMemcpyDeviceToDevice);
}

// round 5
// speedup vs baseline: 2.4137x; 1.1317x over previous
#include <cuda_runtime.h>
#include <mma.h>
#include <math.h>
#include <cstdint>
#include <stdint.h>

using namespace nvcuda;

#define Bn 2
#define Sn 2048
#define Dn 768
#define Hn 12
#define DHn 64
#define Fn 3072
#define Ln 2
#define BSn (Bn*Sn)
#define BHn (Bn*Hn)
#define NTILES 16              // Sn / 128 score column tiles

// ---------------- scratch ----------------
__device__ float g_h  [BSn*Dn];
__device__ float g_qh [BSn*Dn];
__device__ float g_kh [BSn*Dn];
__device__ float g_vh [BSn*Dn];
__device__ float g_o  [BSn*Dn];
__device__ float g_t  [BSn*Dn];
__device__ float g_ff [BSn*Fn];
__device__ float g_smax[BHn*Sn*NTILES];
__device__ float g_ssum[BHn*Sn*NTILES];
__device__ float g_rmax[BHn*Sn];
__device__ float g_rinv[BHn*Sn];

// ---------------- cp.async helpers ----------------
__device__ __forceinline__ void cp_async16(uint32_t saddr, const void* gaddr) {
    asm volatile("cp.async.cg.shared.global [%0], [%1], 16;\n" :: "r"(saddr), "l"(gaddr));
}
#define CP_COMMIT() asm volatile("cp.async.commit_group;\n" ::)
#define CP_WAIT1()  asm volatile("cp.async.wait_group 1;\n" ::)
#define CP_WAIT0()  asm volatile("cp.async.wait_group 0;\n" ::)

// ---------------- embedding + sinusoidal PE ----------------
__global__ void embed_kernel(const int* __restrict__ x, const float* __restrict__ emb,
                             float* __restrict__ h)
{
    int row = blockIdx.x;
    int s   = row % Sn;
    long tok = x[row];
    const float* er = emb + tok * (long)Dn;
    float* hr = h + (long)row * Dn;
    const float c = -logf(10000.0f) / (float)Dn;
    for (int j = threadIdx.x; j < Dn; j += blockDim.x) {
        float div = expf((float)(j & ~1) * c);
        float ang = (float)s * div;
        float pe = (j & 1) ? cosf(ang) : sinf(ang);
        hr[j] = er[j] + pe;
    }
}

// ---------------- pipelined TF32 tensor-core GEMM ----------------
// MODE: 0 plain, 1 heads (QKV -> [b,h,s,d]), 2 merge (AV -> [b,s,D])
// MULTI: z selects among {B0,B1,B2}; STATS: scores epilogue emits softmax partials;
// SMAX: A is raw scores -> normalize on the fly + write probs back to A.
template<int BM, int BN, bool NT, int MODE, bool MULTI, bool STATS, bool SMAX>
__global__ __launch_bounds__(256, 2)
void gemm_tc(const float* __restrict__ A,
             const float* B0, const float* B1, const float* B2,
             const float* bias0, const float* bias1, const float* bias2,
             float* C0, float* C1, float* C2,
             int M, int N, int K, int lda, int ldb, int ldc,
             long sA, long sB, long sC, float alpha, int relu,
             float* st_max, float* st_sum,
             const float* r_max, const float* r_inv)
{
    constexpr int BK = 32;
    constexpr int STAGES = 3;
    constexpr int LDA_S = BK + 4;
    constexpr int LDB_S = NT ? (BK + 4) : (BN + 4);
    constexpr int BROWS = NT ? BN : BK;
    constexpr int LDC_S = BN + 4;
    constexpr int WARPS_M = 4, WARPS_N = 2;
    constexpr int WM = BM / WARPS_M;
    constexpr int WN = BN / WARPS_N;
    constexpr int FM = WM / 16;
    constexpr int FN = WN / 16;

    extern __shared__ char smem_raw[];
    float* As = (float*)smem_raw;                       // [STAGES][BM][LDA_S]
    float* Bs = As + STAGES * BM * LDA_S;               // [STAGES][BROWS][LDB_S]
    float* sm_rmax = Bs + STAGES * BROWS * LDB_S;       // [BM]   (SMAX only)
    float* sm_rinv = sm_rmax + BM;                      // [BM]
    float* Cs = (float*)smem_raw;                       // epilogue alias

    const int z = blockIdx.z;
    const float* Bm; const float* bias; float* C;
    if (MULTI) {
        Bm   = (z == 0) ? B0 : ((z == 1) ? B1 : B2);
        bias = (z == 0) ? bias0 : ((z == 1) ? bias1 : bias2);
        C    = (z == 0) ? C0 : ((z == 1) ? C1 : C2);
    } else {
        Bm   = B0 + z * sB;
        bias = bias0;
        C    = C0 + z * sC;
        A   += z * sA;
    }

    const int bm = blockIdx.y * BM;
    const int bn = blockIdx.x * BN;
    const int tid = threadIdx.x;
    const int warp = tid >> 5;
    const int lane = tid & 31;
    const int wm = (warp % WARPS_M) * WM;
    const int wn = (warp / WARPS_M) * WN;

    if (SMAX) {           // preload row softmax stats (visible after first barrier)
        if (tid < BM) {
            sm_rmax[tid] = r_max[(long)z * Sn + bm + tid];
            sm_rinv[tid] = r_inv[(long)z * Sn + bm + tid];
        }
    }

    const uint32_t sAs = (uint32_t)__cvta_generic_to_shared(As);
    const uint32_t sBs = (uint32_t)__cvta_generic_to_shared(Bs);

    wmma::fragment<wmma::accumulator, 16, 16, 8, float> acc[FM][FN];
#pragma unroll
    for (int i = 0; i < FM; i++)
#pragma unroll
        for (int j = 0; j < FN; j++) wmma::fill_fragment(acc[i][j], 0.0f);

    const int kIters = K / BK;

    auto load_stage = [&](int st, int ki) {
        if (ki >= kIters) return;
        const int k0 = ki * BK;
        constexpr int NVA = BM * BK / 4;
#pragma unroll
        for (int e = tid; e < NVA; e += 256) {
            int m  = e / (BK / 4);
            int kv = (e % (BK / 4)) * 4;
            cp_async16(sAs + ((st * BM + m) * LDA_S + kv) * 4,
                       A + (long)(bm + m) * lda + k0 + kv);
        }
        if (!NT) {
            constexpr int NVB = BK * BN / 4;
#pragma unroll
            for (int e = tid; e < NVB; e += 256) {
                int k  = e / (BN / 4);
                int nv = (e % (BN / 4)) * 4;
                cp_async16(sBs + ((st * BROWS + k) * LDB_S + nv) * 4,
                           Bm + (long)(k0 + k) * ldb + bn + nv);
            }
        } else {
            constexpr int NVB = BN * BK / 4;
#pragma unroll
            for (int e = tid; e < NVB; e += 256) {
                int n  = e / (BK / 4);
                int kv = (e % (BK / 4)) * 4;
                cp_async16(sBs + ((st * BROWS + n) * LDB_S + kv) * 4,
                           Bm + (long)(bn + n) * ldb + k0 + kv);
            }
        }
    };

    for (int s = 0; s < STAGES - 1; s++) { load_stage(s, s); CP_COMMIT(); }

    for (int ki = 0; ki < kIters; ki++) {
        CP_WAIT1();
        __syncthreads();
        load_stage((ki + STAGES - 1) % STAGES, ki + STAGES - 1);
        CP_COMMIT();

        const int st = ki % STAGES;
        float* Ast = As + st * BM * LDA_S;
        const float* Bst = Bs + st * BROWS * LDB_S;

        if (SMAX) {
            // normalize raw scores in smem + write probabilities back to gmem
            const int k0 = ki * BK;
            float* Awb = const_cast<float*>(A);
            constexpr int NVA = BM * BK / 4;
#pragma unroll
            for (int e = tid; e < NVA; e += 256) {
                int m  = e >> 3;
                int kv = (e & 7) * 4;
                float4 s4 = *(float4*)&Ast[m * LDA_S + kv];
                float mx = sm_rmax[m], inv = sm_rinv[m];
                s4.x = __expf(s4.x - mx) * inv;
                s4.y = __expf(s4.y - mx) * inv;
                s4.z = __expf(s4.z - mx) * inv;
                s4.w = __expf(s4.w - mx) * inv;
                *(float4*)&Ast[m * LDA_S + kv] = s4;
                *(float4*)&Awb[(long)(bm + m) * lda + k0 + kv] = s4;
            }
            __syncthreads();
        }

#pragma unroll
        for (int kf = 0; kf < BK / 8; kf++) {
            wmma::fragment<wmma::matrix_a, 16, 16, 8, wmma::precision::tf32, wmma::row_major> af[FM];
#pragma unroll
            for (int i = 0; i < FM; i++) {
                wmma::load_matrix_sync(af[i], Ast + (wm + i * 16) * LDA_S + kf * 8, LDA_S);
#pragma unroll
                for (int e = 0; e < af[i].num_elements; e++)
                    af[i].x[e] = wmma::__float_to_tf32(af[i].x[e]);
            }
            if (!NT) {
                wmma::fragment<wmma::matrix_b, 16, 16, 8, wmma::precision::tf32, wmma::row_major> bf[FN];
#pragma unroll
                for (int j = 0; j < FN; j++) {
                    wmma::load_matrix_sync(bf[j], Bst + (kf * 8) * LDB_S + wn + j * 16, LDB_S);
#pragma unroll
                    for (int e = 0; e < bf[j].num_elements; e++)
                        bf[j].x[e] = wmma::__float_to_tf32(bf[j].x[e]);
                }
#pragma unroll
                for (int i = 0; i < FM; i++)
#pragma unroll
                    for (int j = 0; j < FN; j++)
                        wmma::mma_sync(acc[i][j], af[i], bf[j], acc[i][j]);
            } else {
                wmma::fragment<wmma::matrix_b, 16, 16, 8, wmma::precision::tf32, wmma::col_major> bf[FN];
#pragma unroll
                for (int j = 0; j < FN; j++) {
                    wmma::load_matrix_sync(bf[j], Bst + (wn + j * 16) * LDB_S + kf * 8, LDB_S);
#pragma unroll
                    for (int e = 0; e < bf[j].num_elements; e++)
                        bf[j].x[e] = wmma::__float_to_tf32(bf[j].x[e]);
                }
#pragma unroll
                for (int i = 0; i < FM; i++)
#pragma unroll
                    for (int j = 0; j < FN; j++)
                        wmma::mma_sync(acc[i][j], af[i], bf[j], acc[i][j]);
            }
        }
    }

    CP_WAIT0();
    __syncthreads();

#pragma unroll
    for (int i = 0; i < FM; i++)
#pragma unroll
        for (int j = 0; j < FN; j++)
            wmma::store_matrix_sync(Cs + (wm + i * 16) * LDC_S + wn + j * 16,
                                    acc[i][j], LDC_S, wmma::mem_row_major);
    __syncthreads();

    constexpr int NVC = BM * BN / 4;
    if (STATS) {
        // scores epilogue: store raw tile + per-(row, tile) max & sumexp
#pragma unroll
        for (int p = 0; p < NVC / 256; p++) {
            int e  = tid + p * 256;
            int m  = e / (BN / 4);
            int nv = (e % (BN / 4)) * 4;
            float4 v = *(const float4*)&Cs[m * LDC_S + nv];
            v.x *= alpha; v.y *= alpha; v.z *= alpha; v.w *= alpha;
            *(float4*)&C[(long)(bm + m) * ldc + bn + nv] = v;
            // warp == tile-row: reduce max then sumexp over 128 cols
            float lmax = fmaxf(fmaxf(v.x, v.y), fmaxf(v.z, v.w));
#pragma unroll
            for (int o = 16; o > 0; o >>= 1)
                lmax = fmaxf(lmax, __shfl_xor_sync(0xffffffffu, lmax, o));
            float lsum = __expf(v.x - lmax) + __expf(v.y - lmax) +
                         __expf(v.z - lmax) + __expf(v.w - lmax);
#pragma unroll
            for (int o = 16; o > 0; o >>= 1)
                lsum += __shfl_xor_sync(0xffffffffu, lsum, o);
            if (lane == 0) {
                long idx = ((long)z * Sn + bm + m) * NTILES + blockIdx.x;
                st_max[idx] = lmax;
                st_sum[idx] = lsum;
            }
        }
    } else {
#pragma unroll 4
        for (int e = tid; e < NVC; e += 256) {
            int m  = e / (BN / 4);
            int nv = (e % (BN / 4)) * 4;
            float4 v = *(const float4*)&Cs[m * LDC_S + nv];
            if (alpha != 1.0f) { v.x *= alpha; v.y *= alpha; v.z *= alpha; v.w *= alpha; }
            if (bias) {
                int c = bn + nv;
                v.x += bias[c]; v.y += bias[c + 1]; v.z += bias[c + 2]; v.w += bias[c + 3];
            }
            if (relu) {
                v.x = fmaxf(v.x, 0.f); v.y = fmaxf(v.y, 0.f);
                v.z = fmaxf(v.z, 0.f); v.w = fmaxf(v.w, 0.f);
            }
            if (MODE == 0) {
                *(float4*)&C[(long)(bm + m) * ldc + bn + nv] = v;
            } else if (MODE == 1) {
                int r = bm + m, c = bn + nv;
                int b = r >> 11, s = r & (Sn - 1);
                int hh = c >> 6, d = c & 63;
                *(float4*)&C[((((long)b * Hn + hh) * Sn + s) << 6) + d] = v;
            } else {
                int b = z / Hn, hh = z % Hn;
                *(float4*)&C[((long)(b * Sn + bm + m)) * Dn + hh * DHn + bn + nv] = v;
            }
        }
    }
}

// ---------------- combine per-tile stats into row max / inv-sum ----------------
__global__ void stats_reduce(const float* __restrict__ smax, const float* __restrict__ ssum,
                             float* __restrict__ rmax, float* __restrict__ rinv)
{
    long row = (long)blockIdx.x * blockDim.x + threadIdx.x;
    if (row >= (long)BHn * Sn) return;
    float M = -1e30f;
#pragma unroll
    for (int t = 0; t < NTILES; t++) M = fmaxf(M, smax[row * NTILES + t]);
    float S = 0.f;
#pragma unroll
    for (int t = 0; t < NTILES; t++) S += ssum[row * NTILES + t] * __expf(smax[row * NTILES + t] - M);
    rmax[row] = M;
    rinv[row] = 1.f / S;
}

// ---------------- residual add + LayerNorm ----------------
__global__ void add_ln_kernel(const float* __restrict__ x, const float* __restrict__ d,
                              const float* __restrict__ g, const float* __restrict__ bb,
                              float* __restrict__ out)
{
    int row = blockIdx.x;
    int t = threadIdx.x;
    __shared__ float red[256];
    float v[3];
    float s = 0.f;
#pragma unroll
    for (int i = 0; i < 3; i++) {
        int c = t + i*256;
        v[i] = x[(long)row*Dn + c] + d[(long)row*Dn + c];
        s += v[i];
    }
    red[t] = s; __syncthreads();
    for (int o = 128; o > 0; o >>= 1) { if (t < o) red[t] += red[t+o]; __syncthreads(); }
    float mu = red[0] / (float)Dn;
    __syncthreads();
    float s2 = 0.f;
#pragma unroll
    for (int i = 0; i < 3; i++) { float dv = v[i] - mu; s2 += dv*dv; }
    red[t] = s2; __syncthreads();
    for (int o = 128; o > 0; o >>= 1) { if (t < o) red[t] += red[t+o]; __syncthreads(); }
    float inv = rsqrtf(red[0] / (float)Dn + 1e-5f);
    __syncthreads();
#pragma unroll
    for (int i = 0; i < 3; i++) {
        int c = t + i*256;
        out[(long)row*Dn + c] = (v[i] - mu) * inv * g[c] + bb[c];
    }
}

// ---------------- host side ----------------
#define SYM_PTR(sym) ([]{ void* p_; cudaGetSymbolAddress(&p_, sym); return (float*)p_; }())

#define SMEM_NN128 ((3*(128*36 + 32*132))*4)            // 105984
#define SMEM_NT128 ((3*(128*36 + 128*36))*4)            // 110592
#define SMEM_NN64  ((3*(128*36 + 32*68))*4 + 128*2*4)   // 82432 (incl. row stats)

extern "C" void kernel_launch(void* const* d_in, const int* in_sizes, int n_in,
                              void* d_out, int out_size)
{
    const int*   x    = (const int*)  d_in[0];
    const float* emb  = (const float*)d_in[1];
    const float* Wq   = (const float*)d_in[2];
    const float* bq   = (const float*)d_in[3];
    const float* Wk   = (const float*)d_in[4];
    const float* bk   = (const float*)d_in[5];
    const float* Wv   = (const float*)d_in[6];
    const float* bv   = (const float*)d_in[7];
    const float* Wo   = (const float*)d_in[8];
    const float* bo   = (const float*)d_in[9];
    const float* ln1g = (const float*)d_in[10];
    const float* ln1b = (const float*)d_in[11];
    const float* ln2g = (const float*)d_in[12];
    const float* ln2b = (const float*)d_in[13];
    const float* W1   = (const float*)d_in[14];
    const float* b1   = (const float*)d_in[15];
    const float* W2   = (const float*)d_in[16];
    const float* b2   = (const float*)d_in[17];

    float* out = (float*)d_out;

    float* h   = SYM_PTR(g_h);
    float* qh  = SYM_PTR(g_qh);
    float* kh  = SYM_PTR(g_kh);
    float* vh  = SYM_PTR(g_vh);
    float* o   = SYM_PTR(g_o);
    float* t   = SYM_PTR(g_t);
    float* ff  = SYM_PTR(g_ff);
    float* smax = SYM_PTR(g_smax);
    float* ssum = SYM_PTR(g_ssum);
    float* rmax = SYM_PTR(g_rmax);
    float* rinv = SYM_PTR(g_rinv);

    cudaFuncSetAttribute(gemm_tc<128,128,false,1,true ,false,false>, cudaFuncAttributeMaxDynamicSharedMemorySize, SMEM_NN128);
    cudaFuncSetAttribute(gemm_tc<128,128,false,0,false,false,false>, cudaFuncAttributeMaxDynamicSharedMemorySize, SMEM_NN128);
    cudaFuncSetAttribute(gemm_tc<128,128,true ,0,false,true ,false>, cudaFuncAttributeMaxDynamicSharedMemorySize, SMEM_NT128);
    cudaFuncSetAttribute(gemm_tc<128,64 ,false,2,false,false,true >, cudaFuncAttributeMaxDynamicSharedMemorySize, SMEM_NN64);

    embed_kernel<<<BSn, 256>>>(x, emb, h);

    for (int l = 0; l < Ln; l++) {
        const float* Wq_l = Wq + (long)l*Dn*Dn; const float* bq_l = bq + (long)l*Dn;
        const float* Wk_l = Wk + (long)l*Dn*Dn; const float* bk_l = bk + (long)l*Dn;
        const float* Wv_l = Wv + (long)l*Dn*Dn; const float* bv_l = bv + (long)l*Dn;
        const float* Wo_l = Wo + (long)l*Dn*Dn; const float* bo_l = bo + (long)l*Dn;
        const float* W1_l = W1 + (long)l*Dn*Fn; const float* b1_l = b1 + (long)l*Fn;
        const float* W2_l = W2 + (long)l*Fn*Dn; const float* b2_l = b2 + (long)l*Dn;
        float* maps = out + (long)BSn*Dn + (long)l*Bn*Hn*Sn*Sn;

        // QKV fused -> head layout
        {
            dim3 grid(Dn/128, BSn/128, 3);
            gemm_tc<128,128,false,1,true,false,false><<<grid,256,SMEM_NN128>>>(
                h, Wq_l, Wk_l, Wv_l, bq_l, bk_l, bv_l, qh, kh, vh,
                BSn, Dn, Dn, Dn, Dn, 0, 0,0,0, 1.f, 0,
                nullptr, nullptr, nullptr, nullptr);
        }
        // scores = Q K^T / 8 -> maps (raw) + softmax partial stats
        {
            dim3 grid(Sn/128, Sn/128, BHn);
            gemm_tc<128,128,true,0,false,true,false><<<grid,256,SMEM_NT128>>>(
                qh, kh, nullptr, nullptr, nullptr, nullptr, nullptr,
                maps, nullptr, nullptr,
                Sn, Sn, DHn, DHn, DHn, Sn,
                (long)Sn*DHn, (long)Sn*DHn, (long)Sn*Sn, 0.125f, 0,
                smax, ssum, nullptr, nullptr);
        }
        stats_reduce<<<(BHn*Sn + 255)/256, 256>>>(smax, ssum, rmax, rinv);
        // O = softmax(scores) @ V  (normalize on the fly, write probs back to maps)
        {
            dim3 grid(1, Sn/128, BHn);
            gemm_tc<128,64,false,2,false,false,true><<<grid,256,SMEM_NN64>>>(
                maps, vh, nullptr, nullptr, nullptr, nullptr, nullptr,
                o, nullptr, nullptr,
                Sn, DHn, Sn, Sn, DHn, 0,
                (long)Sn*Sn, (long)Sn*DHn, 0, 1.f, 0,
                nullptr, nullptr, rmax, rinv);
        }
        // attn_out = o @ Wo + bo
        {
            dim3 grid(Dn/128, BSn/128, 1);
            gemm_tc<128,128,false,0,false,false,false><<<grid,256,SMEM_NN128>>>(
                o, Wo_l, nullptr, nullptr, bo_l, nullptr, nullptr,
                t, nullptr, nullptr,
                BSn, Dn, Dn, Dn, Dn, Dn, 0,0,0, 1.f, 0,
                nullptr, nullptr, nullptr, nullptr);
        }
        add_ln_kernel<<<BSn,256>>>(h, t, ln1g + (long)l*Dn, ln1b + (long)l*Dn, h);
        // ff = relu(h @ W1 + b1)
        {
            dim3 grid(Fn/128, BSn/128, 1);
            gemm_tc<128,128,false,0,false,false,false><<<grid,256,SMEM_NN128>>>(
                h, W1_l, nullptr, nullptr, b1_l, nullptr, nullptr,
                ff, nullptr, nullptr,
                BSn, Fn, Dn, Dn, Fn, Fn, 0,0,0, 1.f, 1,
                nullptr, nullptr, nullptr, nullptr);
        }
        // t = ff @ W2 + b2
        {
            dim3 grid(Dn/128, BSn/128, 1);
            gemm_tc<128,128,false,0,false,false,false><<<grid,256,SMEM_NN128>>>(
                ff, W2_l, nullptr, nullptr, b2_l, nullptr, nullptr,
                t, nullptr, nullptr,
                BSn, Dn, Fn, Fn, Dn, Dn, 0,0,0, 1.f, 0,
                nullptr, nullptr, nullptr, nullptr);
        }
        // h = LN2(h + ff_out); last layer writes straight to out
        float* ln_dst = (l == Ln-1) ? out : h;
        add_ln_kernel<<<BSn,256>>>(h, t, ln2g + (long)l*Dn, ln2b + (long)l*Dn, ln_dst);
    }
}